// round 11
// baseline (speedup 1.0000x reference)
#include <cuda_runtime.h>

// Fixed shapes from reference setup_inputs
#define BB    32        // batch
#define TT    4000      // frames per batch
#define NB    65        // nbands
#define LF    129       // FIR length = 2*NB-1
#define FS    80        // framesize (hop)
#define FPB   25        // frames per block tile
#define EF    28        // staged frames (t0-2 .. t0+25)
#define TILES 160       // TT / FPB
#define OUTW  320000    // TT*FS
#define WROW  148       // firwin row stride: 11 zeros + 129 taps + 8 zeros
#define WPAD  11        // left zero pad (band base 132-8c float4-aligned)
#define NTHR  256
#define ZPST  68        // padded T/H row stride (float4-aligned, 68 % 32 = 4 -> conflict-free)
#define XSZ   2520      // swizzled x staging size (2240 + 2240/32*4)
// union region: sT[65*68] + sH[32*68] (4 dummy rows for unguarded rr=3 loads)
#define SUF   (NB * ZPST + 32 * ZPST)   // 6596 floats

__device__ __forceinline__ float hannf(int j) {
    return 0.5f - 0.5f * cospif(2.0f * (float)j * (1.0f / 129.0f));
}

// ---------------- Single fused kernel ----------------
// Per block (one 25-frame tile): build T (cospif), stage H (28 rows),
// GEMM zp = H x T^T with expansion straight into smem firwin rows sW,
// then overlay-stage x and run the R8 conv+overlap-add (at the FFMA floor).
__global__ void __launch_bounds__(NTHR)
fng_all(const float* __restrict__ H, const float* __restrict__ noise,
        float* __restrict__ out) {
    __shared__ __align__(16) float sW[EF * WROW];  // 16576 B (expanded firwin rows)
    __shared__ __align__(16) float sU[SUF];        // 26384 B (phase 1-2: T+H; phase 3+: x)
    float* const sT = sU;                          // [65][68]
    float* const sH = sU + NB * ZPST;              // [32][68] (rows 28..31 dummy)
    float* const sX = sU;                          // overlay after GEMM

    const int tid  = threadIdx.x;
    const int b    = blockIdx.x / TILES;
    const int tile = blockIdx.x - b * TILES;
    const int t0   = tile * FPB;

    // ---- phase 1: zero sW; build cosine table; stage H rows ----
    {
        float4* d4 = reinterpret_cast<float4*>(sW);
        #pragma unroll
        for (int i = tid; i < EF * WROW / 4; i += NTHR)
            d4[i] = make_float4(0.f, 0.f, 0.f, 0.f);
    }
    for (int i = tid; i < NB * NB; i += NTHR) {
        int d = i / NB, k = i - (i / NB) * NB;
        int m = (k * d) % LF;
        float c = cospif(2.0f * (float)m * (1.0f / 129.0f));
        sT[d * ZPST + k] = (k == 0) ? (1.0f / 129.0f) : (2.0f / 129.0f) * c;
    }
    for (int i = tid; i < EF * NB; i += NTHR) {
        int f = i / NB, k = i - f * NB;
        int te = t0 - 2 + f;
        float v = 0.0f;
        if (te >= 0 && te < TT) v = H[((size_t)b * TT + te) * NB + k];
        sH[f * ZPST + k] = v;
    }
    __syncthreads();

    // ---- phase 2: zp GEMM + firwin expansion into sW ----
    // Warp w owns rows {w, w+8, w+16, w+24(<28)}; lane l owns d = l and l+33
    // -> taps {64-l, 64+l, 31-l, 97+l}. d=32 handled by threads 0..27.
    {
        const int w = tid >> 5, l = tid & 31;
        const float h0a = hannf(64 - l);
        const float h0b = hannf(64 + l);
        const float h1a = hannf(31 - l);
        const float h1b = hannf(97 + l);
        const int nr = (w < 4) ? 4 : 3;
        const float* tr0 = &sT[l * ZPST];
        const float* tr1 = &sT[(l + 33) * ZPST];
        float a0[4] = {0,0,0,0}, a1[4] = {0,0,0,0};

        #pragma unroll 4
        for (int kc = 0; kc < 16; ++kc) {
            int k0 = kc * 4;
            float4 t0 = *reinterpret_cast<const float4*>(tr0 + k0);
            float4 t1 = *reinterpret_cast<const float4*>(tr1 + k0);
            #pragma unroll
            for (int rr = 0; rr < 4; ++rr) {      // rr=3 rows >=28 are dummy (guarded at store)
                float4 hv = *reinterpret_cast<const float4*>(&sH[(w + rr * 8) * ZPST + k0]);
                float x0 = a0[rr], x1 = a1[rr];
                x0 = fmaf(hv.x, t0.x, x0); x1 = fmaf(hv.x, t1.x, x1);
                x0 = fmaf(hv.y, t0.y, x0); x1 = fmaf(hv.y, t1.y, x1);
                x0 = fmaf(hv.z, t0.z, x0); x1 = fmaf(hv.z, t1.z, x1);
                x0 = fmaf(hv.w, t0.w, x0); x1 = fmaf(hv.w, t1.w, x1);
                a0[rr] = x0; a1[rr] = x1;
            }
        }
        {   // k = 64 tail
            float t0s = tr0[64], t1s = tr1[64];
            #pragma unroll
            for (int rr = 0; rr < 4; ++rr) {
                float hs = sH[(w + rr * 8) * ZPST + 64];
                a0[rr] = fmaf(hs, t0s, a0[rr]);
                a1[rr] = fmaf(hs, t1s, a1[rr]);
            }
        }
        #pragma unroll
        for (int rr = 0; rr < 4; ++rr) {
            if (rr < nr) {
                int base = (w + rr * 8) * WROW + WPAD;
                sW[base + 64 - l] = a0[rr] * h0a;
                sW[base + 64 + l] = a0[rr] * h0b;
                sW[base + 31 - l] = a1[rr] * h1a;
                sW[base + 97 + l] = a1[rr] * h1b;
            }
        }
    }
    if (tid < EF) {   // d = 32 epilogue: one row per thread -> taps j = 32, 96
        const float* tr = &sT[32 * ZPST];
        const float* hr = &sH[tid * ZPST];
        float s = 0.0f;
        #pragma unroll 5
        for (int k = 0; k < NB; ++k) s = fmaf(hr[k], tr[k], s);
        int base = tid * WROW + WPAD;
        sW[base + 32] = s * hannf(32);
        sW[base + 96] = s * hannf(96);
    }
    __syncthreads();   // sW complete; sT/sH reads done -> safe to overlay

    // ---- phase 3: stage x = 2*noise-1 (overlays sT/sH region) ----
    {
        const int n4 = EF * FS / 4;                    // 560
        const float4* src = reinterpret_cast<const float4*>(
            &noise[(size_t)(b * TT + (tile == 0 ? 0 : t0 - 2)) * FS]);
        const int pad4 = (tile == 0) ? (2 * FS / 4) : 0;
        const int lim4 = (tile == TILES - 1) ? (27 * FS / 4) : n4;
        for (int i = tid; i < n4; i += NTHR) {
            float4 v = (i >= pad4 && i < lim4) ? src[i - pad4] : make_float4(0.5f,0.5f,0.5f,0.5f);
            int i0 = i * 4;
            float4 x = make_float4(2.f*v.x-1.f, 2.f*v.y-1.f, 2.f*v.z-1.f, 2.f*v.w-1.f);
            *reinterpret_cast<float4*>(&sX[i0 + ((i0 >> 5) << 2)]) = x;
        }
    }
    __syncthreads();

    // ---- phase 4: conv + OLA (R8, at scalar-FMA issue floor) ----
    const int groups = (tile == TILES - 1) ? 258 : 250;
    for (int g = tid; g < groups; g += NTHR) {
        if (tile == 0 && g < 8) continue;      // trimmed head
        const int ql0 = g * 8;
        const int sl0 = ql0 + 32;
        int f = sl0 / FS;
        int rem = sl0 - f * FS;
        int cb = (rem == 0) ? 10 : ((FS - rem) >> 3);
        const float* wr = &sW[f * WROW];
        float acc[8] = {0,0,0,0,0,0,0,0};

        #pragma unroll 1
        for (int c = 0; c < 17; ++c) {
            if (c == cb) { wr += WROW; cb += 10; }
            int slc = sl0 + 8 * c;
            int xi = slc + ((slc >> 5) << 2);
            float4 xa = *reinterpret_cast<const float4*>(&sX[xi]);
            float4 xb = *reinterpret_cast<const float4*>(&sX[xi + 4]);
            const float* bp = wr + (132 - 8 * c);
            float4 b0 = *reinterpret_cast<const float4*>(bp);
            float4 b1 = *reinterpret_cast<const float4*>(bp + 4);
            float4 b2 = *reinterpret_cast<const float4*>(bp + 8);
            float4 b3 = *reinterpret_cast<const float4*>(bp + 12);
            float band[16] = {b0.x,b0.y,b0.z,b0.w, b1.x,b1.y,b1.z,b1.w,
                              b2.x,b2.y,b2.z,b2.w, b3.x,b3.y,b3.z,b3.w};
            float xs[8] = {xa.x, xa.y, xa.z, xa.w, xb.x, xb.y, xb.z, xb.w};
            #pragma unroll
            for (int u = 0; u < 8; ++u) {
                float xv = xs[u];
                #pragma unroll
                for (int r = 0; r < 8; ++r)
                    acc[r] = fmaf(xv, band[7 + r - u], acc[r]);
            }
        }

        int p = t0 * FS + ql0 - 64;            // trimmed position, multiple of 8
        float* op = &out[(size_t)b * OUTW + p];
        *reinterpret_cast<float4*>(op)     = make_float4(acc[0], acc[1], acc[2], acc[3]);
        *reinterpret_cast<float4*>(op + 4) = make_float4(acc[4], acc[5], acc[6], acc[7]);
    }
}

extern "C" void kernel_launch(void* const* d_in, const int* in_sizes, int n_in,
                              void* d_out, int out_size) {
    (void)in_sizes; (void)n_in; (void)out_size;
    const float* H     = (const float*)d_in[0];
    const float* noise = (const float*)d_in[1];
    float* out         = (float*)d_out;

    fng_all<<<BB * TILES, NTHR>>>(H, noise, out);
}

// round 12
// speedup vs baseline: 1.1253x; 1.1253x over previous
#include <cuda_runtime.h>

// Fixed shapes from reference setup_inputs
#define BB    32        // batch
#define TT    4000      // frames per batch
#define NB    65        // nbands
#define LF    129       // FIR length = 2*NB-1
#define FS    80        // framesize (hop)
#define FPB   25        // frames per block tile (kernel B)
#define EF    28        // staged frames (t0-2 .. t0+25)
#define TILES 160       // TT / FPB
#define OUTW  320000    // TT*FS
#define WROW  148       // firwin row stride: 11 zeros + 129 taps + 8 zeros
#define WPAD  11        // left zero pad (band base 132-8c float4-aligned)
#define NTHR  256
#define NFRM  (BB*TT)   // 128000 flat frames
#define ZPST  68        // compact zp row stride (float4-aligned; slots 65..67 stay 0)
#define ANF   64        // frames per chunk in kernel A
#define NCH   4         // chunks per block in kernel A
#define ZGRID 500       // 500 blocks x 4 chunks x 64 frames = 128000
#define XSZ   2520      // swizzled x staging size (also hosts sZ overlay: needs >= 1904)

// Compact zp rows [NFRM][68]; slots 65..67 never written -> stay 0 (BSS).
__device__ __align__(16) float g_zp[(size_t)NFRM * ZPST];   // 34.8 MB

__device__ __forceinline__ float hannf(int j) {
    return 0.5f - 0.5f * cospif(2.0f * (float)j * (1.0f / 129.0f));
}

// ---------------- Kernel A: compact zp rows ----------------
// zp[d] = sum_k H[k]*T[d][k]. T built once per block (cospif), 4 chunks/block,
// next chunk's H prefetched into registers during compute (R8 structure).
// Warp w: frames f0=8w..8w+7; lane l: d = l and l+33; d=32 by epilogue.
__global__ void __launch_bounds__(NTHR)
zp_kernel(const float* __restrict__ H) {
    __shared__ __align__(16) float sTa[NB * ZPST];   // 17680 B
    __shared__ __align__(16) float sHa[ANF * ZPST];  // 17408 B

    const int tid = threadIdx.x;

    for (int i = tid; i < NB * NB; i += NTHR) {
        int d = i / NB, k = i - (i / NB) * NB;
        int m = (k * d) % LF;
        float c = cospif(2.0f * (float)m * (1.0f / 129.0f));
        sTa[d * ZPST + k] = (k == 0) ? (1.0f / 129.0f) : (2.0f / 129.0f) * c;
    }

    float hreg[17];
    {
        size_t base = (size_t)(blockIdx.x * ANF) * NB;
        #pragma unroll
        for (int q = 0; q < 17; ++q) {
            int i = tid + NTHR * q;
            hreg[q] = (i < ANF * NB) ? H[base + i] : 0.0f;
        }
    }
    __syncthreads();

    const int w = tid >> 5, l = tid & 31;
    const int f0 = w * 8;
    const float* tr0 = &sTa[l * ZPST];
    const float* tr1 = &sTa[(l + 33) * ZPST];

    for (int ch = 0; ch < NCH; ++ch) {
        const int n0 = blockIdx.x * ANF + ch * (ZGRID * ANF);

        __syncthreads();
        #pragma unroll
        for (int q = 0; q < 17; ++q) {
            int i = tid + NTHR * q;
            if (i < ANF * NB) sHa[(i / NB) * ZPST + (i % NB)] = hreg[q];
        }
        __syncthreads();

        if (ch + 1 < NCH) {
            size_t base = (size_t)(blockIdx.x * ANF + (ch + 1) * (ZGRID * ANF)) * NB;
            #pragma unroll
            for (int q = 0; q < 17; ++q) {
                int i = tid + NTHR * q;
                hreg[q] = (i < ANF * NB) ? H[base + i] : 0.0f;
            }
        }

        float acc0[8] = {0,0,0,0,0,0,0,0};
        float acc1[8] = {0,0,0,0,0,0,0,0};

        #pragma unroll 4
        for (int kc = 0; kc < 16; ++kc) {
            int k0 = kc * 4;
            float4 t0 = *reinterpret_cast<const float4*>(tr0 + k0);
            float4 t1 = *reinterpret_cast<const float4*>(tr1 + k0);
            #pragma unroll
            for (int j = 0; j < 8; ++j) {
                float4 hv = *reinterpret_cast<const float4*>(&sHa[(f0 + j) * ZPST + k0]);
                float a0 = acc0[j], a1 = acc1[j];
                a0 = fmaf(hv.x, t0.x, a0); a1 = fmaf(hv.x, t1.x, a1);
                a0 = fmaf(hv.y, t0.y, a0); a1 = fmaf(hv.y, t1.y, a1);
                a0 = fmaf(hv.z, t0.z, a0); a1 = fmaf(hv.z, t1.z, a1);
                a0 = fmaf(hv.w, t0.w, a0); a1 = fmaf(hv.w, t1.w, a1);
                acc0[j] = a0; acc1[j] = a1;
            }
        }
        {   // k = 64 tail
            float t0s = tr0[64], t1s = tr1[64];
            #pragma unroll
            for (int j = 0; j < 8; ++j) {
                float hs = sHa[(f0 + j) * ZPST + 64];
                acc0[j] = fmaf(hs, t0s, acc0[j]);
                acc1[j] = fmaf(hs, t1s, acc1[j]);
            }
        }

        // compact coalesced stores
        #pragma unroll
        for (int j = 0; j < 8; ++j) {
            size_t row = (size_t)(n0 + f0 + j) * ZPST;
            g_zp[row + l]      = acc0[j];
            g_zp[row + l + 33] = acc1[j];
        }
        if (tid < ANF) {   // d = 32 epilogue
            const float* tr = &sTa[32 * ZPST];
            const float* hr = &sHa[tid * ZPST];
            float s = 0.0f;
            #pragma unroll 5
            for (int k = 0; k < NB; ++k) s = fmaf(hr[k], tr[k], s);
            g_zp[(size_t)(n0 + tid) * ZPST + 32] = s;
        }
    }
}

// ---------------- Kernel B: expand + conv + overlap-add ----------------
__global__ void __launch_bounds__(NTHR)
fng_main(const float* __restrict__ noise, float* __restrict__ out) {
    __shared__ __align__(16) float sW[EF * WROW];  // 16576 B (expanded firwin rows)
    __shared__ __align__(16) float sX[XSZ];        // 10080 B (phase 1-2: sZ overlay; then x)
    float* const sZ = sX;                          // compact zp rows [EF][68]

    const int tid  = threadIdx.x;
    const int b    = blockIdx.x / TILES;
    const int tile = blockIdx.x - b * TILES;
    const int t0   = tile * FPB;

    // ---- phase 1: stage compact zp rows (pure linear float4 copy) ----
    {
        float4* dst = reinterpret_cast<float4*>(sZ);
        const int n4 = EF * ZPST / 4;                  // 476
        const float4* src = reinterpret_cast<const float4*>(
            &g_zp[(size_t)(b * TT + (tile == 0 ? 0 : t0 - 2)) * ZPST]);
        const int pad4 = (tile == 0) ? (2 * ZPST / 4) : 0;           // 34
        const int lim4 = (tile == TILES - 1) ? (27 * ZPST / 4) : n4; // 459
        for (int i = tid; i < n4; i += NTHR)
            dst[i] = (i >= pad4 && i < lim4) ? src[i - pad4] : make_float4(0.f,0.f,0.f,0.f);
    }
    __syncthreads();

    // ---- phase 2: expand into sW; thread t owns column t of all rows ----
    // sW[f][t] = zp[f][|t-75|] * hann(t-11) for t in [11,139], else 0.
    if (tid < WROW) {
        int j = tid - WPAD;
        if ((unsigned)j <= 128u) {
            int d = j - 64; d = (d < 0) ? -d : d;
            float hv = hannf(j);
            #pragma unroll 4
            for (int f = 0; f < EF; ++f)
                sW[f * WROW + tid] = sZ[f * ZPST + d] * hv;
        } else {
            #pragma unroll 4
            for (int f = 0; f < EF; ++f)
                sW[f * WROW + tid] = 0.0f;
        }
    }
    __syncthreads();   // sZ reads done -> safe to overwrite with x

    // ---- phase 3: stage x = 2*noise-1 (linear float4 load, swizzled store) ----
    {
        const int n4 = EF * FS / 4;                    // 560
        const float4* src = reinterpret_cast<const float4*>(
            &noise[(size_t)(b * TT + (tile == 0 ? 0 : t0 - 2)) * FS]);
        const int pad4 = (tile == 0) ? (2 * FS / 4) : 0;
        const int lim4 = (tile == TILES - 1) ? (27 * FS / 4) : n4;
        for (int i = tid; i < n4; i += NTHR) {
            float4 v = (i >= pad4 && i < lim4) ? src[i - pad4] : make_float4(0.5f,0.5f,0.5f,0.5f);
            int i0 = i * 4;
            float4 x = make_float4(2.f*v.x-1.f, 2.f*v.y-1.f, 2.f*v.z-1.f, 2.f*v.w-1.f);
            *reinterpret_cast<float4*>(&sX[i0 + ((i0 >> 5) << 2)]) = x;
        }
    }
    __syncthreads();

    // ---- phase 4: conv + OLA (R8, at scalar-FMA issue floor) ----
    const int groups = (tile == TILES - 1) ? 258 : 250;
    for (int g = tid; g < groups; g += NTHR) {
        if (tile == 0 && g < 8) continue;      // trimmed head
        const int ql0 = g * 8;
        const int sl0 = ql0 + 32;
        int f = sl0 / FS;
        int rem = sl0 - f * FS;
        int cb = (rem == 0) ? 10 : ((FS - rem) >> 3);
        const float* wr = &sW[f * WROW];
        float acc[8] = {0,0,0,0,0,0,0,0};

        #pragma unroll 1
        for (int c = 0; c < 17; ++c) {
            if (c == cb) { wr += WROW; cb += 10; }
            int slc = sl0 + 8 * c;
            int xi = slc + ((slc >> 5) << 2);
            float4 xa = *reinterpret_cast<const float4*>(&sX[xi]);
            float4 xb = *reinterpret_cast<const float4*>(&sX[xi + 4]);
            const float* bp = wr + (132 - 8 * c);
            float4 b0 = *reinterpret_cast<const float4*>(bp);
            float4 b1 = *reinterpret_cast<const float4*>(bp + 4);
            float4 b2 = *reinterpret_cast<const float4*>(bp + 8);
            float4 b3 = *reinterpret_cast<const float4*>(bp + 12);
            float band[16] = {b0.x,b0.y,b0.z,b0.w, b1.x,b1.y,b1.z,b1.w,
                              b2.x,b2.y,b2.z,b2.w, b3.x,b3.y,b3.z,b3.w};
            float xs[8] = {xa.x, xa.y, xa.z, xa.w, xb.x, xb.y, xb.z, xb.w};
            #pragma unroll
            for (int u = 0; u < 8; ++u) {
                float xv = xs[u];
                #pragma unroll
                for (int r = 0; r < 8; ++r)
                    acc[r] = fmaf(xv, band[7 + r - u], acc[r]);
            }
        }

        int p = t0 * FS + ql0 - 64;            // trimmed position, multiple of 8
        float* op = &out[(size_t)b * OUTW + p];
        *reinterpret_cast<float4*>(op)     = make_float4(acc[0], acc[1], acc[2], acc[3]);
        *reinterpret_cast<float4*>(op + 4) = make_float4(acc[4], acc[5], acc[6], acc[7]);
    }
}

extern "C" void kernel_launch(void* const* d_in, const int* in_sizes, int n_in,
                              void* d_out, int out_size) {
    (void)in_sizes; (void)n_in; (void)out_size;
    const float* H     = (const float*)d_in[0];
    const float* noise = (const float*)d_in[1];
    float* out         = (float*)d_out;

    zp_kernel<<<ZGRID, NTHR>>>(H);
    fng_main<<<BB * TILES, NTHR>>>(noise, out);
}

// round 13
// speedup vs baseline: 1.2413x; 1.1031x over previous
#include <cuda_runtime.h>

// Fixed shapes from reference setup_inputs
#define BB    32        // batch
#define TT    4000      // frames per batch
#define NB    65        // nbands
#define LF    129       // FIR length = 2*NB-1
#define FS    80        // framesize (hop)
#define FPB   25        // frames per block tile (kernel B)
#define EF    28        // staged frames (t0-2 .. t0+25)
#define TILES 160       // TT / FPB
#define OUTW  320000    // TT*FS
#define WROW  148       // firwin row stride: 11 zeros + 129 taps + 8 zeros
#define WPAD  11        // left zero pad (band base 132-8c float4-aligned)
#define NTHR  256
#define NFRM  (BB*TT)   // 128000 flat frames
#define ZPST  68        // padded T/H smem row stride (float4-aligned)
#define ANF   64        // frames per chunk in kernel A
#define NCH   4         // chunks per block in kernel A
#define ZGRID 500       // 500 blocks x 4 chunks x 64 frames = 128000
#define XSZ   2520      // swizzled x staging size

// Pre-expanded firwin rows; pads NEVER written -> stay zero (BSS zero-init).
__device__ __align__(16) float g_w[(size_t)NFRM * WROW];   // 75.8 MB

__device__ __forceinline__ float hannf(int j) {
    return 0.5f - 0.5f * cospif(2.0f * (float)j * (1.0f / 129.0f));
}

// ---------------- Kernel A: expanded firwin rows ----------------
// zp[d] = sum_k H[k]*T[d][k];  w[j] = zp[|j-64|]*hann[j].
// 500 blocks x 4 chunks; T built once per block (2D no-div mapping); H for the
// next chunk prefetched into registers during compute; scatter offsets hoisted.
// Warp w: frames f0=8w..8w+7; lane l: d = l, l+33 -> taps {64-l, 64+l, 31-l, 97+l}.
// d=32 (taps 32, 96) via per-warp shfl-butterfly over each warp's own 8 frames.
__global__ void __launch_bounds__(NTHR)
zp_kernel(const float* __restrict__ H) {
    __shared__ __align__(16) float sTa[NB * ZPST];   // 17680 B
    __shared__ __align__(16) float sHa[ANF * ZPST];  // 17408 B

    const int tid = threadIdx.x;
    const int w = tid >> 5, l = tid & 31;
    const int f0 = w * 8;

    // ---- build cosine table: warp w -> rows d = w+8r; lane l -> k = l, l+32 ----
    #pragma unroll
    for (int r = 0; r < 9; ++r) {
        int d = w + 8 * r;
        if (d < NB) {
            int m0 = (l * d) % LF;
            int m1 = ((l + 32) * d) % LF;
            float c0 = cospif(2.0f * (float)m0 * (1.0f / 129.0f));
            float c1 = cospif(2.0f * (float)m1 * (1.0f / 129.0f));
            sTa[d * ZPST + l]      = (l == 0) ? (1.0f / 129.0f) : (2.0f / 129.0f) * c0;
            sTa[d * ZPST + l + 32] = (2.0f / 129.0f) * c1;
            if (l == 0) {
                int m2 = (64 * d) % LF;
                sTa[d * ZPST + 64] = (2.0f / 129.0f) * cospif(2.0f * (float)m2 * (1.0f / 129.0f));
            }
        }
    }

    // ---- hoisted scatter offsets (chunk-invariant) ----
    int soff[17];
    #pragma unroll
    for (int q = 0; q < 17; ++q) {
        int i = tid + NTHR * q;
        int f = i / NB;                  // const-divisor mul-shift
        soff[q] = f * ZPST + (i - f * NB);
    }

    // ---- prefetch chunk 0 H into registers (linear, coalesced) ----
    float hreg[17];
    {
        size_t base = (size_t)(blockIdx.x * ANF) * NB;
        #pragma unroll
        for (int q = 0; q < 17; ++q) {
            int i = tid + NTHR * q;
            hreg[q] = (i < ANF * NB) ? H[base + i] : 0.0f;
        }
    }

    // per-lane constants (no smem deps)
    const float h0a = hannf(64 - l);
    const float h0b = hannf(64 + l);
    const float h1a = hannf(31 - l);
    const float h1b = hannf(97 + l);
    const float h32a = hannf(32), h32b = hannf(96);

    __syncthreads();   // table complete

    const float* tr0 = &sTa[l * ZPST];
    const float* tr1 = &sTa[(l + 33) * ZPST];
    const float* tr32 = &sTa[32 * ZPST];
    const float t32a = tr32[l], t32b = tr32[l + 32], t64c = tr32[64];

    for (int ch = 0; ch < NCH; ++ch) {
        const int n0 = blockIdx.x * ANF + ch * (ZGRID * ANF);

        if (ch) __syncthreads();   // prior chunk's sHa reads done
        #pragma unroll
        for (int q = 0; q < 16; ++q) sHa[soff[q]] = hreg[q];
        if (tid < 64) sHa[soff[16]] = hreg[16];
        __syncthreads();

        // prefetch next chunk while computing this one
        if (ch + 1 < NCH) {
            size_t base = (size_t)(blockIdx.x * ANF + (ch + 1) * (ZGRID * ANF)) * NB;
            #pragma unroll
            for (int q = 0; q < 17; ++q) {
                int i = tid + NTHR * q;
                hreg[q] = (i < ANF * NB) ? H[base + i] : 0.0f;
            }
        }

        float acc0[8] = {0,0,0,0,0,0,0,0};
        float acc1[8] = {0,0,0,0,0,0,0,0};

        #pragma unroll 4
        for (int kc = 0; kc < 16; ++kc) {
            int k0 = kc * 4;
            float4 t0 = *reinterpret_cast<const float4*>(tr0 + k0);
            float4 t1 = *reinterpret_cast<const float4*>(tr1 + k0);
            #pragma unroll
            for (int j = 0; j < 8; ++j) {
                float4 hv = *reinterpret_cast<const float4*>(&sHa[(f0 + j) * ZPST + k0]);
                float a0 = acc0[j], a1 = acc1[j];
                a0 = fmaf(hv.x, t0.x, a0); a1 = fmaf(hv.x, t1.x, a1);
                a0 = fmaf(hv.y, t0.y, a0); a1 = fmaf(hv.y, t1.y, a1);
                a0 = fmaf(hv.z, t0.z, a0); a1 = fmaf(hv.z, t1.z, a1);
                a0 = fmaf(hv.w, t0.w, a0); a1 = fmaf(hv.w, t1.w, a1);
                acc0[j] = a0; acc1[j] = a1;
            }
        }
        {   // k = 64 tail
            float t0s = tr0[64], t1s = tr1[64];
            #pragma unroll
            for (int j = 0; j < 8; ++j) {
                float hs = sHa[(f0 + j) * ZPST + 64];
                acc0[j] = fmaf(hs, t0s, acc0[j]);
                acc1[j] = fmaf(hs, t1s, acc1[j]);
            }
        }

        // ---- expanded firwin stores (4 coalesced groups per frame row) ----
        #pragma unroll
        for (int j = 0; j < 8; ++j) {
            size_t row = (size_t)(n0 + f0 + j) * WROW + WPAD;
            g_w[row + 64 - l] = acc0[j] * h0a;
            g_w[row + 64 + l] = acc0[j] * h0b;
            g_w[row + 31 - l] = acc1[j] * h1a;
            g_w[row + 97 + l] = acc1[j] * h1b;
        }

        // ---- d = 32 epilogue: per-warp shfl reduction over own 8 frames ----
        #pragma unroll
        for (int j = 0; j < 8; ++j) {
            const float* hr = &sHa[(f0 + j) * ZPST];
            float p = fmaf(hr[l], t32a, hr[l + 32] * t32b);   // k = l, l+32
            p += __shfl_xor_sync(0xFFFFFFFFu, p, 1);
            p += __shfl_xor_sync(0xFFFFFFFFu, p, 2);
            p += __shfl_xor_sync(0xFFFFFFFFu, p, 4);
            p += __shfl_xor_sync(0xFFFFFFFFu, p, 8);
            p += __shfl_xor_sync(0xFFFFFFFFu, p, 16);
            float s = p + hr[64] * t64c;                       // k = 64
            size_t row = (size_t)(n0 + f0 + j) * WROW + WPAD;
            if (l == 0) g_w[row + 32] = s * h32a;
            if (l == 1) g_w[row + 96] = s * h32b;
        }
    }
}

// ---------------- Kernel B: conv + overlap-add (R8 verbatim, at FFMA floor) ----------------
__global__ void __launch_bounds__(NTHR)
fng_main(const float* __restrict__ noise, float* __restrict__ out) {
    __shared__ __align__(16) float sW[EF * WROW];  // 16576 B (pre-expanded rows)
    __shared__ __align__(16) float sX[XSZ];        // 10080 B (linear + (s>>5)*4 swizzle)

    const int tid  = threadIdx.x;
    const int b    = blockIdx.x / TILES;
    const int tile = blockIdx.x - b * TILES;
    const int t0   = tile * FPB;

    // ---- stage firwin rows: pure linear float4 copy ----
    {
        float4* dst = reinterpret_cast<float4*>(sW);
        const int n4 = EF * WROW / 4;                  // 1036
        if (tile == 0) {
            const float4* s0 = reinterpret_cast<const float4*>(&g_w[(size_t)b * TT * WROW]);
            const int pad4 = 2 * WROW / 4;             // 74
            for (int i = tid; i < n4; i += NTHR)
                dst[i] = (i < pad4) ? make_float4(0.f,0.f,0.f,0.f) : s0[i - pad4];
        } else if (tile == TILES - 1) {
            const float4* src = reinterpret_cast<const float4*>(
                &g_w[(size_t)(b * TT + t0 - 2) * WROW]);
            const int lim4 = 27 * WROW / 4;            // 999
            for (int i = tid; i < n4; i += NTHR)
                dst[i] = (i < lim4) ? src[i] : make_float4(0.f,0.f,0.f,0.f);
        } else {
            const float4* src = reinterpret_cast<const float4*>(
                &g_w[(size_t)(b * TT + t0 - 2) * WROW]);
            for (int i = tid; i < n4; i += NTHR)
                dst[i] = src[i];
        }
    }
    // ---- stage x = 2*noise-1: linear float4 load, swizzled float4 store ----
    {
        const int n4 = EF * FS / 4;                    // 560
        const float4* src = reinterpret_cast<const float4*>(
            &noise[(size_t)(b * TT + (tile == 0 ? 0 : t0 - 2)) * FS]);
        const int pad4 = (tile == 0) ? (2 * FS / 4) : 0;
        const int lim4 = (tile == TILES - 1) ? (27 * FS / 4) : n4;
        for (int i = tid; i < n4; i += NTHR) {
            float4 v = (i >= pad4 && i < lim4) ? src[i - pad4] : make_float4(0.5f,0.5f,0.5f,0.5f);
            int i0 = i * 4;
            float4 x = make_float4(2.f*v.x-1.f, 2.f*v.y-1.f, 2.f*v.z-1.f, 2.f*v.w-1.f);
            *reinterpret_cast<float4*>(&sX[i0 + ((i0 >> 5) << 2)]) = x;
        }
    }
    __syncthreads();

    // ---- conv + OLA: thread owns 8 consecutive pre-trim outputs q = 80*t0 + 8g + r ----
    const int groups = (tile == TILES - 1) ? 258 : 250;
    for (int g = tid; g < groups; g += NTHR) {
        if (tile == 0 && g < 8) continue;      // trimmed head
        const int ql0 = g * 8;
        const int sl0 = ql0 + 32;
        int f = sl0 / FS;
        int rem = sl0 - f * FS;
        int cb = (rem == 0) ? 10 : ((FS - rem) >> 3);
        const float* wr = &sW[f * WROW];
        float acc[8] = {0,0,0,0,0,0,0,0};

        #pragma unroll 1
        for (int c = 0; c < 17; ++c) {
            if (c == cb) { wr += WROW; cb += 10; }
            int slc = sl0 + 8 * c;
            int xi = slc + ((slc >> 5) << 2);
            float4 xa = *reinterpret_cast<const float4*>(&sX[xi]);
            float4 xb = *reinterpret_cast<const float4*>(&sX[xi + 4]);
            const float* bp = wr + (132 - 8 * c);
            float4 b0 = *reinterpret_cast<const float4*>(bp);
            float4 b1 = *reinterpret_cast<const float4*>(bp + 4);
            float4 b2 = *reinterpret_cast<const float4*>(bp + 8);
            float4 b3 = *reinterpret_cast<const float4*>(bp + 12);
            float band[16] = {b0.x,b0.y,b0.z,b0.w, b1.x,b1.y,b1.z,b1.w,
                              b2.x,b2.y,b2.z,b2.w, b3.x,b3.y,b3.z,b3.w};
            float xs[8] = {xa.x, xa.y, xa.z, xa.w, xb.x, xb.y, xb.z, xb.w};
            #pragma unroll
            for (int u = 0; u < 8; ++u) {
                float xv = xs[u];
                #pragma unroll
                for (int r = 0; r < 8; ++r)
                    acc[r] = fmaf(xv, band[7 + r - u], acc[r]);
            }
        }

        int p = t0 * FS + ql0 - 64;            // trimmed position, multiple of 8
        float* op = &out[(size_t)b * OUTW + p];
        *reinterpret_cast<float4*>(op)     = make_float4(acc[0], acc[1], acc[2], acc[3]);
        *reinterpret_cast<float4*>(op + 4) = make_float4(acc[4], acc[5], acc[6], acc[7]);
    }
}

extern "C" void kernel_launch(void* const* d_in, const int* in_sizes, int n_in,
                              void* d_out, int out_size) {
    (void)in_sizes; (void)n_in; (void)out_size;
    const float* H     = (const float*)d_in[0];
    const float* noise = (const float*)d_in[1];
    float* out         = (float*)d_out;

    zp_kernel<<<ZGRID, NTHR>>>(H);
    fng_main<<<BB * TILES, NTHR>>>(noise, out);
}

// round 15
// speedup vs baseline: 1.3214x; 1.0645x over previous
#include <cuda_runtime.h>

// Fixed shapes from reference setup_inputs
#define BB    32        // batch
#define TT    4000      // frames per batch
#define NB    65        // nbands
#define LF    129       // FIR length = 2*NB-1
#define FS    80        // framesize (hop)
#define FPB   25        // frames per block tile (conv side)
#define EF    28        // staged frames (t0-2 .. t0+25)
#define TILES 160       // TT / FPB
#define OUTW  320000    // TT*FS
#define WROW  148       // firwin row stride: 11 zeros + 129 taps + 8 zeros
#define WPAD  11        // left zero pad (band base 132-8c float4-aligned)
#define NTHR  256
#define NFRM  (BB*TT)   // 128000 flat frames
#define ZPST  68        // padded T/H smem row stride (float4-aligned)
#define ANF   64        // frames per chunk (producer)
#define NCH   4         // chunks per producer block = segments
#define ZBLK  500       // producer blocks; chunk ch of all blocks tiles segment ch
#define XSZ   2520      // swizzled x staging size
#define SBUF  8772      // union smem floats: max(129*68, 28*148+2520)

// Pre-expanded firwin rows; pads NEVER written -> stay zero (BSS zero-init).
__device__ __align__(16) float g_w[(size_t)NFRM * WROW];   // 75.8 MB
__device__ unsigned g_ctr[NCH];   // per-segment completion counters

__global__ void reset_ctr_k() {
    if (threadIdx.x < NCH) g_ctr[threadIdx.x] = 0u;
}

__device__ __forceinline__ float hannf(int j) {
    return 0.5f - 0.5f * cospif(2.0f * (float)j * (1.0f / 129.0f));
}

// ---------------- mega kernel: producers (bids 0..499) + consumers ----------------
__global__ void __launch_bounds__(NTHR, 5)
fng_mega(const float* __restrict__ H, const float* __restrict__ noise,
         float* __restrict__ out) {
    __shared__ __align__(16) float sBuf[SBUF];   // 35088 B
    const int tid = threadIdx.x;

    if (blockIdx.x < ZBLK) {
        // ================= producer: expanded firwin rows (R13 zp) =================
        float* const sTa = sBuf;                 // [65][68]
        float* const sHa = sBuf + NB * ZPST;     // [64][68]
        const int w = tid >> 5, l = tid & 31;
        const int f0 = w * 8;

        // build cosine table: warp w -> rows d = w+8r; lane l -> k = l, l+32
        #pragma unroll
        for (int r = 0; r < 9; ++r) {
            int d = w + 8 * r;
            if (d < NB) {
                int m0 = (l * d) % LF;
                int m1 = ((l + 32) * d) % LF;
                float c0 = cospif(2.0f * (float)m0 * (1.0f / 129.0f));
                float c1 = cospif(2.0f * (float)m1 * (1.0f / 129.0f));
                sTa[d * ZPST + l]      = (l == 0) ? (1.0f / 129.0f) : (2.0f / 129.0f) * c0;
                sTa[d * ZPST + l + 32] = (2.0f / 129.0f) * c1;
                if (l == 0) {
                    int m2 = (64 * d) % LF;
                    sTa[d * ZPST + 64] = (2.0f / 129.0f) * cospif(2.0f * (float)m2 * (1.0f / 129.0f));
                }
            }
        }

        int soff[17];
        #pragma unroll
        for (int q = 0; q < 17; ++q) {
            int i = tid + NTHR * q;
            int f = i / NB;
            soff[q] = f * ZPST + (i - f * NB);
        }

        float hreg[17];
        {
            size_t base = (size_t)(blockIdx.x * ANF) * NB;
            #pragma unroll
            for (int q = 0; q < 17; ++q) {
                int i = tid + NTHR * q;
                hreg[q] = (i < ANF * NB) ? H[base + i] : 0.0f;
            }
        }

        const float h0a = hannf(64 - l);
        const float h0b = hannf(64 + l);
        const float h1a = hannf(31 - l);
        const float h1b = hannf(97 + l);
        const float h32a = hannf(32), h32b = hannf(96);

        __syncthreads();   // table complete

        const float* tr0 = &sTa[l * ZPST];
        const float* tr1 = &sTa[(l + 33) * ZPST];
        const float* tr32 = &sTa[32 * ZPST];
        const float t32a = tr32[l], t32b = tr32[l + 32], t64c = tr32[64];

        for (int ch = 0; ch < NCH; ++ch) {
            const int n0 = blockIdx.x * ANF + ch * (ZBLK * ANF);   // segment ch

            #pragma unroll
            for (int q = 0; q < 16; ++q) sHa[soff[q]] = hreg[q];
            if (tid < 64) sHa[soff[16]] = hreg[16];
            __syncthreads();

            if (ch + 1 < NCH) {
                size_t base = (size_t)(blockIdx.x * ANF + (ch + 1) * (ZBLK * ANF)) * NB;
                #pragma unroll
                for (int q = 0; q < 17; ++q) {
                    int i = tid + NTHR * q;
                    hreg[q] = (i < ANF * NB) ? H[base + i] : 0.0f;
                }
            }

            float acc0[8] = {0,0,0,0,0,0,0,0};
            float acc1[8] = {0,0,0,0,0,0,0,0};

            #pragma unroll 4
            for (int kc = 0; kc < 16; ++kc) {
                int k0 = kc * 4;
                float4 t0 = *reinterpret_cast<const float4*>(tr0 + k0);
                float4 t1 = *reinterpret_cast<const float4*>(tr1 + k0);
                #pragma unroll
                for (int j = 0; j < 8; ++j) {
                    float4 hv = *reinterpret_cast<const float4*>(&sHa[(f0 + j) * ZPST + k0]);
                    float a0 = acc0[j], a1 = acc1[j];
                    a0 = fmaf(hv.x, t0.x, a0); a1 = fmaf(hv.x, t1.x, a1);
                    a0 = fmaf(hv.y, t0.y, a0); a1 = fmaf(hv.y, t1.y, a1);
                    a0 = fmaf(hv.z, t0.z, a0); a1 = fmaf(hv.z, t1.z, a1);
                    a0 = fmaf(hv.w, t0.w, a0); a1 = fmaf(hv.w, t1.w, a1);
                    acc0[j] = a0; acc1[j] = a1;
                }
            }
            {   // k = 64 tail
                float t0s = tr0[64], t1s = tr1[64];
                #pragma unroll
                for (int j = 0; j < 8; ++j) {
                    float hs = sHa[(f0 + j) * ZPST + 64];
                    acc0[j] = fmaf(hs, t0s, acc0[j]);
                    acc1[j] = fmaf(hs, t1s, acc1[j]);
                }
            }

            #pragma unroll
            for (int j = 0; j < 8; ++j) {
                size_t row = (size_t)(n0 + f0 + j) * WROW + WPAD;
                g_w[row + 64 - l] = acc0[j] * h0a;
                g_w[row + 64 + l] = acc0[j] * h0b;
                g_w[row + 31 - l] = acc1[j] * h1a;
                g_w[row + 97 + l] = acc1[j] * h1b;
            }
            #pragma unroll
            for (int j = 0; j < 8; ++j) {   // d = 32 -> taps 32, 96 via shfl butterfly
                const float* hr = &sHa[(f0 + j) * ZPST];
                float p = fmaf(hr[l], t32a, hr[l + 32] * t32b);
                p += __shfl_xor_sync(0xFFFFFFFFu, p, 1);
                p += __shfl_xor_sync(0xFFFFFFFFu, p, 2);
                p += __shfl_xor_sync(0xFFFFFFFFu, p, 4);
                p += __shfl_xor_sync(0xFFFFFFFFu, p, 8);
                p += __shfl_xor_sync(0xFFFFFFFFu, p, 16);
                float s = p + hr[64] * t64c;
                size_t row = (size_t)(n0 + f0 + j) * WROW + WPAD;
                if (l == 0) g_w[row + 32] = s * h32a;
                if (l == 1) g_w[row + 96] = s * h32b;
            }

            // publish segment ch
            __threadfence();
            __syncthreads();   // all threads' stores fenced; also guards sHa reuse
            if (tid == 0) atomicAdd(&g_ctr[ch], 1u);
        }
        return;
    }

    // ================= consumer: conv + overlap-add (R8) =================
    {
        float* const sW = sBuf;              // [EF][WROW] = 4144 floats
        float* const sX = sBuf + EF * WROW;  // 2520 floats

        const int idx  = blockIdx.x - ZBLK;
        const int b    = idx / TILES;
        const int tile = idx - b * TILES;
        const int t0   = tile * FPB;
        const int seg  = b >> 3;

        // wait for producer segment
        if (tid == 0) {
            unsigned v;
            while (true) {
                asm volatile("ld.acquire.gpu.u32 %0, [%1];" : "=r"(v) : "l"(&g_ctr[seg]) : "memory");
                if (v >= (unsigned)ZBLK) break;
                __nanosleep(512);
            }
        }
        __syncthreads();

        // stage firwin rows: pure linear float4 copy
        {
            float4* dst = reinterpret_cast<float4*>(sW);
            const int n4 = EF * WROW / 4;                  // 1036
            if (tile == 0) {
                const float4* s0 = reinterpret_cast<const float4*>(&g_w[(size_t)b * TT * WROW]);
                const int pad4 = 2 * WROW / 4;
                for (int i = tid; i < n4; i += NTHR)
                    dst[i] = (i < pad4) ? make_float4(0.f,0.f,0.f,0.f) : s0[i - pad4];
            } else if (tile == TILES - 1) {
                const float4* src = reinterpret_cast<const float4*>(
                    &g_w[(size_t)(b * TT + t0 - 2) * WROW]);
                const int lim4 = 27 * WROW / 4;
                for (int i = tid; i < n4; i += NTHR)
                    dst[i] = (i < lim4) ? src[i] : make_float4(0.f,0.f,0.f,0.f);
            } else {
                const float4* src = reinterpret_cast<const float4*>(
                    &g_w[(size_t)(b * TT + t0 - 2) * WROW]);
                for (int i = tid; i < n4; i += NTHR)
                    dst[i] = src[i];
            }
        }
        // stage x = 2*noise-1
        {
            const int n4 = EF * FS / 4;                    // 560
            const float4* src = reinterpret_cast<const float4*>(
                &noise[(size_t)(b * TT + (tile == 0 ? 0 : t0 - 2)) * FS]);
            const int pad4 = (tile == 0) ? (2 * FS / 4) : 0;
            const int lim4 = (tile == TILES - 1) ? (27 * FS / 4) : n4;
            for (int i = tid; i < n4; i += NTHR) {
                float4 v = (i >= pad4 && i < lim4) ? src[i - pad4] : make_float4(0.5f,0.5f,0.5f,0.5f);
                int i0 = i * 4;
                float4 x = make_float4(2.f*v.x-1.f, 2.f*v.y-1.f, 2.f*v.z-1.f, 2.f*v.w-1.f);
                *reinterpret_cast<float4*>(&sX[i0 + ((i0 >> 5) << 2)]) = x;
            }
        }
        __syncthreads();

        // conv + OLA
        const int groups = (tile == TILES - 1) ? 258 : 250;
        for (int g = tid; g < groups; g += NTHR) {
            if (tile == 0 && g < 8) continue;
            const int ql0 = g * 8;
            const int sl0 = ql0 + 32;
            int f = sl0 / FS;
            int rem = sl0 - f * FS;
            int cb = (rem == 0) ? 10 : ((FS - rem) >> 3);
            const float* wr = &sW[f * WROW];
            float acc[8] = {0,0,0,0,0,0,0,0};

            #pragma unroll 1
            for (int c = 0; c < 17; ++c) {
                if (c == cb) { wr += WROW; cb += 10; }
                int slc = sl0 + 8 * c;
                int xi = slc + ((slc >> 5) << 2);
                float4 xa = *reinterpret_cast<const float4*>(&sX[xi]);
                float4 xb = *reinterpret_cast<const float4*>(&sX[xi + 4]);
                const float* bp = wr + (132 - 8 * c);
                float4 b0 = *reinterpret_cast<const float4*>(bp);
                float4 b1 = *reinterpret_cast<const float4*>(bp + 4);
                float4 b2 = *reinterpret_cast<const float4*>(bp + 8);
                float4 b3 = *reinterpret_cast<const float4*>(bp + 12);
                float band[16] = {b0.x,b0.y,b0.z,b0.w, b1.x,b1.y,b1.z,b1.w,
                                  b2.x,b2.y,b2.z,b2.w, b3.x,b3.y,b3.z,b3.w};
                float xs[8] = {xa.x, xa.y, xa.z, xa.w, xb.x, xb.y, xb.z, xb.w};
                #pragma unroll
                for (int u = 0; u < 8; ++u) {
                    float xv = xs[u];
                    #pragma unroll
                    for (int r = 0; r < 8; ++r)
                        acc[r] = fmaf(xv, band[7 + r - u], acc[r]);
                }
            }

            int p = t0 * FS + ql0 - 64;
            float* op = &out[(size_t)b * OUTW + p];
            *reinterpret_cast<float4*>(op)     = make_float4(acc[0], acc[1], acc[2], acc[3]);
            *reinterpret_cast<float4*>(op + 4) = make_float4(acc[4], acc[5], acc[6], acc[7]);
        }
    }
}

extern "C" void kernel_launch(void* const* d_in, const int* in_sizes, int n_in,
                              void* d_out, int out_size) {
    (void)in_sizes; (void)n_in; (void)out_size;
    const float* H     = (const float*)d_in[0];
    const float* noise = (const float*)d_in[1];
    float* out         = (float*)d_out;

    reset_ctr_k<<<1, 32>>>();
    fng_mega<<<ZBLK + BB * TILES, NTHR>>>(H, noise, out);
}